// round 13
// baseline (speedup 1.0000x reference)
#include <cuda_runtime.h>
#include <cuda_fp16.h>
#include <cstdint>

#define BB 4
#define SS 4096
#define DE 768
#define DH 64
#define QT 128
#define KT 128

// fp16 scratch for projected Q (pre-scaled), K, V.
__device__ __half g_qh[BB * SS * DH];
__device__ __half g_kh[BB * SS * DH];
__device__ __half g_vh[BB * SS * DH];
// compacted (unmasked-only, zero-padded to 128 multiple) K/V + counts
__device__ __half g_kc[BB * SS * DH];
__device__ __half g_vc[BB * SS * DH];
__device__ int    g_cnt[BB];

// ---------------------------------------------------------------------------
// helpers
// ---------------------------------------------------------------------------
__device__ __forceinline__ uint32_t f2tf32(float x) {
    uint32_t r;
    asm("cvt.rna.tf32.f32 %0, %1;" : "=r"(r) : "f"(x));
    return r;
}
__device__ __forceinline__ float ex2f(float x) {
    float y; asm("ex2.approx.f32 %0, %1;" : "=f"(y) : "f"(x)); return y;
}
__device__ __forceinline__ void mma8(float* d, const uint32_t* a, const uint32_t* b) {
    asm volatile(
        "mma.sync.aligned.m16n8k8.row.col.f32.tf32.tf32.f32 "
        "{%0,%1,%2,%3}, {%4,%5,%6,%7}, {%8,%9}, {%0,%1,%2,%3};"
        : "+f"(d[0]), "+f"(d[1]), "+f"(d[2]), "+f"(d[3])
        : "r"(a[0]), "r"(a[1]), "r"(a[2]), "r"(a[3]), "r"(b[0]), "r"(b[1]));
}
__device__ __forceinline__ void mma16(float* d, const uint32_t* a, uint32_t b0, uint32_t b1) {
    asm volatile(
        "mma.sync.aligned.m16n8k16.row.col.f32.f16.f16.f32 "
        "{%0,%1,%2,%3}, {%4,%5,%6,%7}, {%8,%9}, {%0,%1,%2,%3};"
        : "+f"(d[0]), "+f"(d[1]), "+f"(d[2]), "+f"(d[3])
        : "r"(a[0]), "r"(a[1]), "r"(a[2]), "r"(a[3]), "r"(b0), "r"(b1));
}
__device__ __forceinline__ void ldmx4(uint32_t* r, uint32_t addr) {
    asm volatile("ldmatrix.sync.aligned.m8n8.x4.shared.b16 {%0,%1,%2,%3}, [%4];"
        : "=r"(r[0]), "=r"(r[1]), "=r"(r[2]), "=r"(r[3]) : "r"(addr));
}
__device__ __forceinline__ void ldmx2(uint32_t& r0, uint32_t& r1, uint32_t addr) {
    asm volatile("ldmatrix.sync.aligned.m8n8.x2.shared.b16 {%0,%1}, [%2];"
        : "=r"(r0), "=r"(r1) : "r"(addr));
}
__device__ __forceinline__ void ldmx2t(uint32_t& r0, uint32_t& r1, uint32_t addr) {
    asm volatile("ldmatrix.sync.aligned.m8n8.x2.trans.shared.b16 {%0,%1}, [%2];"
        : "=r"(r0), "=r"(r1) : "r"(addr));
}
__device__ __forceinline__ uint32_t packh2(float lo, float hi) {
    __half2 h = __floats2half2_rn(lo, hi);
    return *(uint32_t*)&h;
}
__device__ __forceinline__ void cpasync16(uint32_t dst, const void* src) {
    asm volatile("cp.async.cg.shared.global [%0], [%1], 16;"
        :: "r"(dst), "l"(src) : "memory");
}
#define CP_COMMIT() asm volatile("cp.async.commit_group;" ::: "memory")
#define CP_WAIT0()  asm volatile("cp.async.wait_group 0;" ::: "memory")

// ===========================================================================
// Fused QKV projection, tf32 mma.sync + cp.async double-buffered pipeline.
// C[16384,192] = X @ [Wq|Wk|Wv] + bias -> fp16 (Q pre-scaled by log2e/8).
// grid 128, 256 threads = 8 warps (4m x 2n), BK=32, 24 iterations.
// ===========================================================================
#define XS_STR 36
#define WS_STR 200
#define QKV_NIT (DE / 32)

__global__ __launch_bounds__(256) void qkv_mma(
    const float* __restrict__ X,
    const float* __restrict__ Wq, const float* __restrict__ bq,
    const float* __restrict__ Wk, const float* __restrict__ bk,
    const float* __restrict__ Wv, const float* __restrict__ bv)
{
    extern __shared__ char qsm[];
    float* XsA[2] = { (float*)qsm, (float*)(qsm + 18432) };            // 128 x 36 f32 each
    float* WsA[2] = { (float*)(qsm + 36864), (float*)(qsm + 62464) };  // 32 x 200 f32 each
    float* bsm    = (float*)(qsm + 88064);                             // 192 f32

    const int tid = threadIdx.x;
    const int wid = tid >> 5, lane = tid & 31;
    const int g = lane >> 2, tg = lane & 3;
    const int warp_m = wid & 3, warp_n = wid >> 2;
    const int r0 = warp_m * 32;
    const int n0 = warp_n * 96;
    const int m0 = blockIdx.x * 128;

    const uint32_t xs_b[2] = { (uint32_t)__cvta_generic_to_shared(XsA[0]),
                               (uint32_t)__cvta_generic_to_shared(XsA[1]) };
    const uint32_t ws_b[2] = { (uint32_t)__cvta_generic_to_shared(WsA[0]),
                               (uint32_t)__cvta_generic_to_shared(WsA[1]) };

    if (tid < 192)
        bsm[tid] = (tid < 64) ? bq[tid] : (tid < 128) ? bk[tid - 64] : bv[tid - 128];

    // ---- prefetch tile 0 ----
    {
        #pragma unroll
        for (int i = 0; i < 4; i++) {
            int idx = tid + i * 256;
            int r = idx >> 3, c4 = (idx & 7) * 4;
            cpasync16(xs_b[0] + ((uint32_t)(r * XS_STR + c4)) * 4u,
                      &X[(size_t)(m0 + r) * DE + c4]);
        }
        #pragma unroll
        for (int i = 0; i < 6; i++) {
            int idx = tid + i * 256;
            int kr = idx / 48, col = (idx % 48) * 4;
            int mtx = col >> 6, cc = col & 63;
            const float* W = (mtx == 0) ? Wq : (mtx == 1) ? Wk : Wv;
            cpasync16(ws_b[0] + ((uint32_t)(kr * WS_STR + col)) * 4u,
                      &W[(size_t)kr * DH + cc]);
        }
        CP_COMMIT();
    }

    float acc[2][12][4];
    #pragma unroll
    for (int m = 0; m < 2; m++)
        #pragma unroll
        for (int n = 0; n < 12; n++)
            #pragma unroll
            for (int i = 0; i < 4; i++) acc[m][n][i] = 0.f;

    for (int kc = 0; kc < QKV_NIT; kc++) {
        const int p = kc & 1;
        CP_WAIT0();
        __syncthreads();

        // prefetch next tile (overlaps compute below)
        if (kc + 1 < QKV_NIT) {
            const int k1 = (kc + 1) * 32, p1 = p ^ 1;
            #pragma unroll
            for (int i = 0; i < 4; i++) {
                int idx = tid + i * 256;
                int r = idx >> 3, c4 = (idx & 7) * 4;
                cpasync16(xs_b[p1] + ((uint32_t)(r * XS_STR + c4)) * 4u,
                          &X[(size_t)(m0 + r) * DE + k1 + c4]);
            }
            #pragma unroll
            for (int i = 0; i < 6; i++) {
                int idx = tid + i * 256;
                int kr = idx / 48, col = (idx % 48) * 4;
                int mtx = col >> 6, cc = col & 63;
                const float* W = (mtx == 0) ? Wq : (mtx == 1) ? Wk : Wv;
                cpasync16(ws_b[p1] + ((uint32_t)(kr * WS_STR + col)) * 4u,
                          &W[(size_t)(k1 + kr) * DH + cc]);
            }
            CP_COMMIT();
        }

        const float* Xs = XsA[p];
        const float* Ws = WsA[p];
        #pragma unroll
        for (int kf = 0; kf < 4; kf++) {
            uint32_t a[2][4];
            #pragma unroll
            for (int m = 0; m < 2; m++) {
                int r = r0 + m * 16 + g;
                a[m][0] = f2tf32(Xs[r * XS_STR + kf * 8 + tg]);
                a[m][1] = f2tf32(Xs[(r + 8) * XS_STR + kf * 8 + tg]);
                a[m][2] = f2tf32(Xs[r * XS_STR + kf * 8 + tg + 4]);
                a[m][3] = f2tf32(Xs[(r + 8) * XS_STR + kf * 8 + tg + 4]);
            }
            #pragma unroll
            for (int nf = 0; nf < 12; nf++) {
                uint32_t b[2];
                b[0] = f2tf32(Ws[(kf * 8 + tg) * WS_STR + n0 + nf * 8 + g]);
                b[1] = f2tf32(Ws[(kf * 8 + tg + 4) * WS_STR + n0 + nf * 8 + g]);
                mma8(acc[0][nf], a[0], b);
                mma8(acc[1][nf], a[1], b);
            }
        }
    }

    const float SCL = 0.18033688011112042f;   // log2(e)/sqrt(64)
    #pragma unroll
    for (int m = 0; m < 2; m++) {
        #pragma unroll
        for (int nf = 0; nf < 12; nf++) {
            int col = n0 + nf * 8 + 2 * tg;
            int mtx = col >> 6, cc = col & 63;
            __half* C = (mtx == 0) ? g_qh : (mtx == 1) ? g_kh : g_vh;
            float s = (mtx == 0) ? SCL : 1.f;
            float b0 = bsm[col], b1 = bsm[col + 1];
            int ra = m0 + r0 + m * 16 + g;
            uint32_t u0 = packh2((acc[m][nf][0] + b0) * s, (acc[m][nf][1] + b1) * s);
            uint32_t u1 = packh2((acc[m][nf][2] + b0) * s, (acc[m][nf][3] + b1) * s);
            *(uint32_t*)&C[(size_t)ra * DH + cc] = u0;
            *(uint32_t*)&C[(size_t)(ra + 8) * DH + cc] = u1;
        }
    }
}

// ===========================================================================
// Compaction: gather unmasked K/V rows, zero-pad to 128 multiple.
// ===========================================================================
__global__ __launch_bounds__(1024) void compact_kernel(const int* __restrict__ mask)
{
    __shared__ int slist[SS];
    __shared__ int wsum[32];

    const int b = blockIdx.x;
    const int tid = threadIdx.x;
    const int lane = tid & 31, wid = tid >> 5;

    int k0 = tid * 4;
    int m0 = mask[b * SS + k0 + 0];
    int m1 = mask[b * SS + k0 + 1];
    int m2 = mask[b * SS + k0 + 2];
    int m3 = mask[b * SS + k0 + 3];
    int lsum = (m0 != 0) + (m1 != 0) + (m2 != 0) + (m3 != 0);

    int v = lsum;
    #pragma unroll
    for (int off = 1; off < 32; off <<= 1) {
        int t = __shfl_up_sync(0xffffffffu, v, off);
        if (lane >= off) v += t;
    }
    if (lane == 31) wsum[wid] = v;
    __syncthreads();
    if (wid == 0) {
        int w = wsum[lane];
        #pragma unroll
        for (int off = 1; off < 32; off <<= 1) {
            int t = __shfl_up_sync(0xffffffffu, w, off);
            if (lane >= off) w += t;
        }
        wsum[lane] = w;
    }
    __syncthreads();
    int base = (wid > 0 ? wsum[wid - 1] : 0) + (v - lsum);
    int p = base;
    if (m0) slist[p++] = k0 + 0;
    if (m1) slist[p++] = k0 + 1;
    if (m2) slist[p++] = k0 + 2;
    if (m3) slist[p++] = k0 + 3;
    const int count = wsum[31];
    if (tid == 0) g_cnt[b] = count;
    __syncthreads();

    const int padded = (count + 127) & ~127;
    for (int rb = 0; rb < padded; rb += 128) {
        int j = rb + (tid >> 3);
        int ch = tid & 7;
        if (j < padded) {
            uint4 z = make_uint4(0, 0, 0, 0);
            uint4 kv = z, vv = z;
            if (j < count) {
                int src = slist[j];
                kv = *(const uint4*)&g_kh[(size_t)(b * SS + src) * DH + ch * 8];
                vv = *(const uint4*)&g_vh[(size_t)(b * SS + src) * DH + ch * 8];
            }
            *(uint4*)&g_kc[(size_t)(b * SS + j) * DH + ch * 8] = kv;
            *(uint4*)&g_vc[(size_t)(b * SS + j) * DH + ch * 8] = vv;
        }
    }
}

// ===========================================================================
// Attention over compacted keys (unchanged from R12).
// ===========================================================================
#define KV_STRH 72
#define OB_STR 72

__global__ __launch_bounds__(256, 1) void attn_mma(float* __restrict__ out)
{
    extern __shared__ char smc[];
    __half* KsA[2] = { (__half*)smc, (__half*)(smc + 18432) };
    __half* VsA[2] = { (__half*)(smc + 36864), (__half*)(smc + 55296) };
    float* lsum   = (float*)(smc + 73728);
    float* Obuf   = (float*)smc;
    __half* Qstg  = VsA[1];

    const int tid = threadIdx.x;
    const int wid = tid >> 5, lane = tid & 31;
    const int g = lane >> 2, tg = lane & 3;
    const int warp_m = wid & 3, warp_n = wid >> 2;
    const int r0 = warp_m * 32;
    const int n0 = warp_n * 64;
    const int b = blockIdx.y;
    const int q0 = blockIdx.x * QT;

    const int count = g_cnt[b];
    const int nt = (count + KT - 1) / KT;

    const uint32_t ks_b[2] = { (uint32_t)__cvta_generic_to_shared(KsA[0]),
                               (uint32_t)__cvta_generic_to_shared(KsA[1]) };
    const uint32_t vs_b[2] = { (uint32_t)__cvta_generic_to_shared(VsA[0]),
                               (uint32_t)__cvta_generic_to_shared(VsA[1]) };

    #pragma unroll
    for (int i = 0; i < 4; i++) {
        int idx = tid + i * 256;
        int r = idx >> 3, c = idx & 7;
        uint4 v = *(const uint4*)&g_qh[(size_t)(b * SS + q0 + r) * DH + c * 8];
        *(uint4*)&Qstg[r * KV_STRH + c * 8] = v;
    }
    __syncthreads();

    uint32_t qa[2][4][4];
    {
        uint32_t qbase = vs_b[1];
        #pragma unroll
        for (int m = 0; m < 2; m++)
            #pragma unroll
            for (int s = 0; s < 4; s++) {
                uint32_t a = qbase +
                    ((uint32_t)((r0 + m * 16 + (lane & 15)) * KV_STRH + 16 * s + ((lane >> 4) * 8))) * 2u;
                ldmx4(qa[m][s], a);
            }
    }
    __syncthreads();

    {
        #pragma unroll
        for (int i = 0; i < 4; i++) {
            int idx = tid + i * 256;
            int r = idx >> 3, c = idx & 7;
            uint32_t off = ((uint32_t)(r * KV_STRH + c * 8)) * 2u;
            cpasync16(ks_b[0] + off, &g_kc[(size_t)(b * SS + r) * DH + c * 8]);
            cpasync16(vs_b[0] + off, &g_vc[(size_t)(b * SS + r) * DH + c * 8]);
        }
        CP_COMMIT();
    }

    float oacc[2][8][4];
    #pragma unroll
    for (int m = 0; m < 2; m++)
        #pragma unroll
        for (int n = 0; n < 8; n++)
            #pragma unroll
            for (int i = 0; i < 4; i++) oacc[m][n][i] = 0.f;
    float rs_acc[2][2] = {{0.f, 0.f}, {0.f, 0.f}};

    for (int kt = 0; kt < nt; kt++) {
        const int p = kt & 1;
        const int k0 = kt * KT;
        CP_WAIT0();
        __syncthreads();

        if (kt + 1 < nt) {
            const int k1 = (kt + 1) * KT, p1 = p ^ 1;
            #pragma unroll
            for (int i = 0; i < 4; i++) {
                int idx = tid + i * 256;
                int r = idx >> 3, c = idx & 7;
                uint32_t off = ((uint32_t)(r * KV_STRH + c * 8)) * 2u;
                cpasync16(ks_b[p1] + off, &g_kc[(size_t)(b * SS + k1 + r) * DH + c * 8]);
                cpasync16(vs_b[p1] + off, &g_vc[(size_t)(b * SS + k1 + r) * DH + c * 8]);
            }
            CP_COMMIT();
        }

        float sacc[2][8][4];
        #pragma unroll
        for (int m = 0; m < 2; m++)
            #pragma unroll
            for (int n = 0; n < 8; n++)
                #pragma unroll
                for (int i = 0; i < 4; i++) sacc[m][n][i] = 0.f;

        #pragma unroll
        for (int s = 0; s < 4; s++) {
            #pragma unroll
            for (int nf = 0; nf < 8; nf++) {
                uint32_t b0, b1;
                uint32_t a = ks_b[p] +
                    ((uint32_t)((n0 + nf * 8 + (lane & 7)) * KV_STRH + 16 * s + (((lane >> 3) & 1) * 8))) * 2u;
                ldmx2(b0, b1, a);
                mma16(sacc[0][nf], qa[0][s], b0, b1);
                mma16(sacc[1][nf], qa[1][s], b0, b1);
            }
        }

        const int rem = count - k0;
        #pragma unroll
        for (int m = 0; m < 2; m++) {
            #pragma unroll
            for (int nf = 0; nf < 8; nf++) {
                int c = n0 + nf * 8 + 2 * tg;
                float mk0 = (c < rem) ? 1.f : 0.f;
                float mk1 = (c + 1 < rem) ? 1.f : 0.f;
                float p0 = ex2f(sacc[m][nf][0]) * mk0;
                float p1 = ex2f(sacc[m][nf][1]) * mk1;
                float p2 = ex2f(sacc[m][nf][2]) * mk0;
                float p3 = ex2f(sacc[m][nf][3]) * mk1;
                sacc[m][nf][0] = p0; sacc[m][nf][1] = p1;
                sacc[m][nf][2] = p2; sacc[m][nf][3] = p3;
                rs_acc[m][0] += p0 + p1;
                rs_acc[m][1] += p2 + p3;
            }
        }

        #pragma unroll
        for (int s = 0; s < 4; s++) {
            uint32_t pa0[4], pa1[4];
            pa0[0] = packh2(sacc[0][2 * s][0],     sacc[0][2 * s][1]);
            pa0[1] = packh2(sacc[0][2 * s][2],     sacc[0][2 * s][3]);
            pa0[2] = packh2(sacc[0][2 * s + 1][0], sacc[0][2 * s + 1][1]);
            pa0[3] = packh2(sacc[0][2 * s + 1][2], sacc[0][2 * s + 1][3]);
            pa1[0] = packh2(sacc[1][2 * s][0],     sacc[1][2 * s][1]);
            pa1[1] = packh2(sacc[1][2 * s][2],     sacc[1][2 * s][3]);
            pa1[2] = packh2(sacc[1][2 * s + 1][0], sacc[1][2 * s + 1][1]);
            pa1[3] = packh2(sacc[1][2 * s + 1][2], sacc[1][2 * s + 1][3]);
            #pragma unroll
            for (int nf = 0; nf < 8; nf++) {
                uint32_t b0, b1;
                uint32_t a = vs_b[p] +
                    ((uint32_t)((n0 + 16 * s + (lane & 15)) * KV_STRH + nf * 8)) * 2u;
                ldmx2t(b0, b1, a);
                mma16(oacc[0][nf], pa0, b0, b1);
                mma16(oacc[1][nf], pa1, b0, b1);
            }
        }
    }
    __syncthreads();

    #pragma unroll
    for (int m = 0; m < 2; m++)
        #pragma unroll
        for (int h = 0; h < 2; h++) {
            float v = rs_acc[m][h];
            v += __shfl_xor_sync(0xffffffffu, v, 1);
            v += __shfl_xor_sync(0xffffffffu, v, 2);
            if (tg == 0) lsum[warp_n * 128 + r0 + m * 16 + h * 8 + g] = v;
        }
    __syncthreads();

    if (warp_n == 0) {
        #pragma unroll
        for (int m = 0; m < 2; m++)
            #pragma unroll
            for (int nf = 0; nf < 8; nf++) {
                int r = r0 + m * 16 + g, c = nf * 8 + 2 * tg;
                *(float2*)&Obuf[r * OB_STR + c] =
                    make_float2(oacc[m][nf][0], oacc[m][nf][1]);
                *(float2*)&Obuf[(r + 8) * OB_STR + c] =
                    make_float2(oacc[m][nf][2], oacc[m][nf][3]);
            }
    }
    __syncthreads();
    if (warp_n == 1) {
        #pragma unroll
        for (int m = 0; m < 2; m++)
            #pragma unroll
            for (int nf = 0; nf < 8; nf++) {
                int r = r0 + m * 16 + g, c = nf * 8 + 2 * tg;
                float2 t0 = *(float2*)&Obuf[r * OB_STR + c];
                float2 t1 = *(float2*)&Obuf[(r + 8) * OB_STR + c];
                t0.x += oacc[m][nf][0]; t0.y += oacc[m][nf][1];
                t1.x += oacc[m][nf][2]; t1.y += oacc[m][nf][3];
                *(float2*)&Obuf[r * OB_STR + c] = t0;
                *(float2*)&Obuf[(r + 8) * OB_STR + c] = t1;
            }
    }
    __syncthreads();

    #pragma unroll
    for (int i = 0; i < 8; i++) {
        int idx = tid + i * 256;
        int r = idx >> 4, d4 = (idx & 15) * 4;
        float inv = 1.f / (lsum[r] + lsum[128 + r]);
        float4 v;
        v.x = Obuf[r * OB_STR + d4 + 0] * inv;
        v.y = Obuf[r * OB_STR + d4 + 1] * inv;
        v.z = Obuf[r * OB_STR + d4 + 2] * inv;
        v.w = Obuf[r * OB_STR + d4 + 3] * inv;
        *(float4*)&out[(size_t)(b * SS + q0 + r) * DH + d4] = v;
    }
}

// ===========================================================================
extern "C" void kernel_launch(void* const* d_in, const int* in_sizes, int n_in,
                              void* d_out, int out_size)
{
    const float* x  = (const float*)d_in[0];
    const int* mask = (const int*)d_in[1];
    const float* Wq = (const float*)d_in[2];
    const float* bq = (const float*)d_in[3];
    const float* Wk = (const float*)d_in[4];
    const float* bk = (const float*)d_in[5];
    const float* Wv = (const float*)d_in[6];
    const float* bv = (const float*)d_in[7];
    float* out = (float*)d_out;

    const int qsmem = 88064 + 192 * 4;   // 88832
    cudaFuncSetAttribute(qkv_mma, cudaFuncAttributeMaxDynamicSharedMemorySize, qsmem);
    qkv_mma<<<BB * SS / 128, 256, qsmem>>>(x, Wq, bq, Wk, bk, Wv, bv);

    compact_kernel<<<BB, 1024>>>(mask);

    const int smem = 73728 + 1024;   // 74752
    cudaFuncSetAttribute(attn_mma, cudaFuncAttributeMaxDynamicSharedMemorySize, smem);
    dim3 g2(SS / QT, BB);
    attn_mma<<<g2, 256, smem>>>(out);
}

// round 14
// speedup vs baseline: 1.0101x; 1.0101x over previous
#include <cuda_runtime.h>
#include <cuda_fp16.h>
#include <cstdint>

#define BB 4
#define SS 4096
#define DE 768
#define DH 64
#define QT 128
#define KT 128

// fp16 scratch for projected Q (pre-scaled), K, V.
__device__ __half g_qh[BB * SS * DH];
__device__ __half g_kh[BB * SS * DH];
__device__ __half g_vh[BB * SS * DH];
// compacted (unmasked-only, zero-padded to 128 multiple) K/V + counts
__device__ __half g_kc[BB * SS * DH];
__device__ __half g_vc[BB * SS * DH];
__device__ int    g_cnt[BB];

// ---------------------------------------------------------------------------
// helpers
// ---------------------------------------------------------------------------
__device__ __forceinline__ uint32_t f2tf32(float x) {
    uint32_t r;
    asm("cvt.rna.tf32.f32 %0, %1;" : "=r"(r) : "f"(x));
    return r;
}
__device__ __forceinline__ float ex2f(float x) {
    float y; asm("ex2.approx.f32 %0, %1;" : "=f"(y) : "f"(x)); return y;
}
__device__ __forceinline__ void mma8(float* d, const uint32_t* a, const uint32_t* b) {
    asm volatile(
        "mma.sync.aligned.m16n8k8.row.col.f32.tf32.tf32.f32 "
        "{%0,%1,%2,%3}, {%4,%5,%6,%7}, {%8,%9}, {%0,%1,%2,%3};"
        : "+f"(d[0]), "+f"(d[1]), "+f"(d[2]), "+f"(d[3])
        : "r"(a[0]), "r"(a[1]), "r"(a[2]), "r"(a[3]), "r"(b[0]), "r"(b[1]));
}
__device__ __forceinline__ void mma16(float* d, const uint32_t* a, uint32_t b0, uint32_t b1) {
    asm volatile(
        "mma.sync.aligned.m16n8k16.row.col.f32.f16.f16.f32 "
        "{%0,%1,%2,%3}, {%4,%5,%6,%7}, {%8,%9}, {%0,%1,%2,%3};"
        : "+f"(d[0]), "+f"(d[1]), "+f"(d[2]), "+f"(d[3])
        : "r"(a[0]), "r"(a[1]), "r"(a[2]), "r"(a[3]), "r"(b0), "r"(b1));
}
__device__ __forceinline__ void ldmx4(uint32_t* r, uint32_t addr) {
    asm volatile("ldmatrix.sync.aligned.m8n8.x4.shared.b16 {%0,%1,%2,%3}, [%4];"
        : "=r"(r[0]), "=r"(r[1]), "=r"(r[2]), "=r"(r[3]) : "r"(addr));
}
__device__ __forceinline__ void ldmx2(uint32_t& r0, uint32_t& r1, uint32_t addr) {
    asm volatile("ldmatrix.sync.aligned.m8n8.x2.shared.b16 {%0,%1}, [%2];"
        : "=r"(r0), "=r"(r1) : "r"(addr));
}
__device__ __forceinline__ void ldmx2t(uint32_t& r0, uint32_t& r1, uint32_t addr) {
    asm volatile("ldmatrix.sync.aligned.m8n8.x2.trans.shared.b16 {%0,%1}, [%2];"
        : "=r"(r0), "=r"(r1) : "r"(addr));
}
__device__ __forceinline__ uint32_t packh2(float lo, float hi) {
    __half2 h = __floats2half2_rn(lo, hi);
    return *(uint32_t*)&h;
}
__device__ __forceinline__ void cpasync16(uint32_t dst, const void* src) {
    asm volatile("cp.async.cg.shared.global [%0], [%1], 16;"
        :: "r"(dst), "l"(src) : "memory");
}
#define CP_COMMIT() asm volatile("cp.async.commit_group;" ::: "memory")
#define CP_WAIT0()  asm volatile("cp.async.wait_group 0;" ::: "memory")

// ===========================================================================
// Fused QKV projection, tf32 mma.sync + cp.async double-buffered pipeline.
// C[16384,192] = X @ [Wq|Wk|Wv] + bias -> fp16 (Q pre-scaled by log2e/8).
// grid 128, 256 threads = 8 warps (4m x 2n), BK=32, 24 iterations.
// ===========================================================================
#define XS_STR 36
#define WS_STR 200
#define QKV_NIT (DE / 32)

__global__ __launch_bounds__(256) void qkv_mma(
    const float* __restrict__ X,
    const float* __restrict__ Wq, const float* __restrict__ bq,
    const float* __restrict__ Wk, const float* __restrict__ bk,
    const float* __restrict__ Wv, const float* __restrict__ bv)
{
    extern __shared__ char qsm[];
    float* XsA[2] = { (float*)qsm, (float*)(qsm + 18432) };            // 128 x 36 f32 each
    float* WsA[2] = { (float*)(qsm + 36864), (float*)(qsm + 62464) };  // 32 x 200 f32 each
    float* bsm    = (float*)(qsm + 88064);                             // 192 f32

    const int tid = threadIdx.x;
    const int wid = tid >> 5, lane = tid & 31;
    const int g = lane >> 2, tg = lane & 3;
    const int warp_m = wid & 3, warp_n = wid >> 2;
    const int r0 = warp_m * 32;
    const int n0 = warp_n * 96;
    const int m0 = blockIdx.x * 128;

    const uint32_t xs_b[2] = { (uint32_t)__cvta_generic_to_shared(XsA[0]),
                               (uint32_t)__cvta_generic_to_shared(XsA[1]) };
    const uint32_t ws_b[2] = { (uint32_t)__cvta_generic_to_shared(WsA[0]),
                               (uint32_t)__cvta_generic_to_shared(WsA[1]) };

    if (tid < 192)
        bsm[tid] = (tid < 64) ? bq[tid] : (tid < 128) ? bk[tid - 64] : bv[tid - 128];

    // ---- prefetch tile 0 ----
    {
        #pragma unroll
        for (int i = 0; i < 4; i++) {
            int idx = tid + i * 256;
            int r = idx >> 3, c4 = (idx & 7) * 4;
            cpasync16(xs_b[0] + ((uint32_t)(r * XS_STR + c4)) * 4u,
                      &X[(size_t)(m0 + r) * DE + c4]);
        }
        #pragma unroll
        for (int i = 0; i < 6; i++) {
            int idx = tid + i * 256;
            int kr = idx / 48, col = (idx % 48) * 4;
            int mtx = col >> 6, cc = col & 63;
            const float* W = (mtx == 0) ? Wq : (mtx == 1) ? Wk : Wv;
            cpasync16(ws_b[0] + ((uint32_t)(kr * WS_STR + col)) * 4u,
                      &W[(size_t)kr * DH + cc]);
        }
        CP_COMMIT();
    }

    float acc[2][12][4];
    #pragma unroll
    for (int m = 0; m < 2; m++)
        #pragma unroll
        for (int n = 0; n < 12; n++)
            #pragma unroll
            for (int i = 0; i < 4; i++) acc[m][n][i] = 0.f;

    for (int kc = 0; kc < QKV_NIT; kc++) {
        const int p = kc & 1;
        CP_WAIT0();
        __syncthreads();

        // prefetch next tile (overlaps compute below)
        if (kc + 1 < QKV_NIT) {
            const int k1 = (kc + 1) * 32, p1 = p ^ 1;
            #pragma unroll
            for (int i = 0; i < 4; i++) {
                int idx = tid + i * 256;
                int r = idx >> 3, c4 = (idx & 7) * 4;
                cpasync16(xs_b[p1] + ((uint32_t)(r * XS_STR + c4)) * 4u,
                          &X[(size_t)(m0 + r) * DE + k1 + c4]);
            }
            #pragma unroll
            for (int i = 0; i < 6; i++) {
                int idx = tid + i * 256;
                int kr = idx / 48, col = (idx % 48) * 4;
                int mtx = col >> 6, cc = col & 63;
                const float* W = (mtx == 0) ? Wq : (mtx == 1) ? Wk : Wv;
                cpasync16(ws_b[p1] + ((uint32_t)(kr * WS_STR + col)) * 4u,
                          &W[(size_t)(k1 + kr) * DH + cc]);
            }
            CP_COMMIT();
        }

        const float* Xs = XsA[p];
        const float* Ws = WsA[p];
        #pragma unroll
        for (int kf = 0; kf < 4; kf++) {
            uint32_t a[2][4];
            #pragma unroll
            for (int m = 0; m < 2; m++) {
                int r = r0 + m * 16 + g;
                a[m][0] = f2tf32(Xs[r * XS_STR + kf * 8 + tg]);
                a[m][1] = f2tf32(Xs[(r + 8) * XS_STR + kf * 8 + tg]);
                a[m][2] = f2tf32(Xs[r * XS_STR + kf * 8 + tg + 4]);
                a[m][3] = f2tf32(Xs[(r + 8) * XS_STR + kf * 8 + tg + 4]);
            }
            #pragma unroll
            for (int nf = 0; nf < 12; nf++) {
                uint32_t b[2];
                b[0] = f2tf32(Ws[(kf * 8 + tg) * WS_STR + n0 + nf * 8 + g]);
                b[1] = f2tf32(Ws[(kf * 8 + tg + 4) * WS_STR + n0 + nf * 8 + g]);
                mma8(acc[0][nf], a[0], b);
                mma8(acc[1][nf], a[1], b);
            }
        }
    }

    const float SCL = 0.18033688011112042f;   // log2(e)/sqrt(64)
    #pragma unroll
    for (int m = 0; m < 2; m++) {
        #pragma unroll
        for (int nf = 0; nf < 12; nf++) {
            int col = n0 + nf * 8 + 2 * tg;
            int mtx = col >> 6, cc = col & 63;
            __half* C = (mtx == 0) ? g_qh : (mtx == 1) ? g_kh : g_vh;
            float s = (mtx == 0) ? SCL : 1.f;
            float b0 = bsm[col], b1 = bsm[col + 1];
            int ra = m0 + r0 + m * 16 + g;
            uint32_t u0 = packh2((acc[m][nf][0] + b0) * s, (acc[m][nf][1] + b1) * s);
            uint32_t u1 = packh2((acc[m][nf][2] + b0) * s, (acc[m][nf][3] + b1) * s);
            *(uint32_t*)&C[(size_t)ra * DH + cc] = u0;
            *(uint32_t*)&C[(size_t)(ra + 8) * DH + cc] = u1;
        }
    }
}

// ===========================================================================
// Compaction: gather unmasked K/V rows, zero-pad to 128 multiple.
// ===========================================================================
__global__ __launch_bounds__(1024) void compact_kernel(const int* __restrict__ mask)
{
    __shared__ int slist[SS];
    __shared__ int wsum[32];

    const int b = blockIdx.x;
    const int tid = threadIdx.x;
    const int lane = tid & 31, wid = tid >> 5;

    int k0 = tid * 4;
    int m0 = mask[b * SS + k0 + 0];
    int m1 = mask[b * SS + k0 + 1];
    int m2 = mask[b * SS + k0 + 2];
    int m3 = mask[b * SS + k0 + 3];
    int lsum = (m0 != 0) + (m1 != 0) + (m2 != 0) + (m3 != 0);

    int v = lsum;
    #pragma unroll
    for (int off = 1; off < 32; off <<= 1) {
        int t = __shfl_up_sync(0xffffffffu, v, off);
        if (lane >= off) v += t;
    }
    if (lane == 31) wsum[wid] = v;
    __syncthreads();
    if (wid == 0) {
        int w = wsum[lane];
        #pragma unroll
        for (int off = 1; off < 32; off <<= 1) {
            int t = __shfl_up_sync(0xffffffffu, w, off);
            if (lane >= off) w += t;
        }
        wsum[lane] = w;
    }
    __syncthreads();
    int base = (wid > 0 ? wsum[wid - 1] : 0) + (v - lsum);
    int p = base;
    if (m0) slist[p++] = k0 + 0;
    if (m1) slist[p++] = k0 + 1;
    if (m2) slist[p++] = k0 + 2;
    if (m3) slist[p++] = k0 + 3;
    const int count = wsum[31];
    if (tid == 0) g_cnt[b] = count;
    __syncthreads();

    const int padded = (count + 127) & ~127;
    for (int rb = 0; rb < padded; rb += 128) {
        int j = rb + (tid >> 3);
        int ch = tid & 7;
        if (j < padded) {
            uint4 z = make_uint4(0, 0, 0, 0);
            uint4 kv = z, vv = z;
            if (j < count) {
                int src = slist[j];
                kv = *(const uint4*)&g_kh[(size_t)(b * SS + src) * DH + ch * 8];
                vv = *(const uint4*)&g_vh[(size_t)(b * SS + src) * DH + ch * 8];
            }
            *(uint4*)&g_kc[(size_t)(b * SS + j) * DH + ch * 8] = kv;
            *(uint4*)&g_vc[(size_t)(b * SS + j) * DH + ch * 8] = vv;
        }
    }
}

// ===========================================================================
// Attention over compacted keys (unchanged from R12).
// ===========================================================================
#define KV_STRH 72
#define OB_STR 72

__global__ __launch_bounds__(256, 1) void attn_mma(float* __restrict__ out)
{
    extern __shared__ char smc[];
    __half* KsA[2] = { (__half*)smc, (__half*)(smc + 18432) };
    __half* VsA[2] = { (__half*)(smc + 36864), (__half*)(smc + 55296) };
    float* lsum   = (float*)(smc + 73728);
    float* Obuf   = (float*)smc;
    __half* Qstg  = VsA[1];

    const int tid = threadIdx.x;
    const int wid = tid >> 5, lane = tid & 31;
    const int g = lane >> 2, tg = lane & 3;
    const int warp_m = wid & 3, warp_n = wid >> 2;
    const int r0 = warp_m * 32;
    const int n0 = warp_n * 64;
    const int b = blockIdx.y;
    const int q0 = blockIdx.x * QT;

    const int count = g_cnt[b];
    const int nt = (count + KT - 1) / KT;

    const uint32_t ks_b[2] = { (uint32_t)__cvta_generic_to_shared(KsA[0]),
                               (uint32_t)__cvta_generic_to_shared(KsA[1]) };
    const uint32_t vs_b[2] = { (uint32_t)__cvta_generic_to_shared(VsA[0]),
                               (uint32_t)__cvta_generic_to_shared(VsA[1]) };

    #pragma unroll
    for (int i = 0; i < 4; i++) {
        int idx = tid + i * 256;
        int r = idx >> 3, c = idx & 7;
        uint4 v = *(const uint4*)&g_qh[(size_t)(b * SS + q0 + r) * DH + c * 8];
        *(uint4*)&Qstg[r * KV_STRH + c * 8] = v;
    }
    __syncthreads();

    uint32_t qa[2][4][4];
    {
        uint32_t qbase = vs_b[1];
        #pragma unroll
        for (int m = 0; m < 2; m++)
            #pragma unroll
            for (int s = 0; s < 4; s++) {
                uint32_t a = qbase +
                    ((uint32_t)((r0 + m * 16 + (lane & 15)) * KV_STRH + 16 * s + ((lane >> 4) * 8))) * 2u;
                ldmx4(qa[m][s], a);
            }
    }
    __syncthreads();

    {
        #pragma unroll
        for (int i = 0; i < 4; i++) {
            int idx = tid + i * 256;
            int r = idx >> 3, c = idx & 7;
            uint32_t off = ((uint32_t)(r * KV_STRH + c * 8)) * 2u;
            cpasync16(ks_b[0] + off, &g_kc[(size_t)(b * SS + r) * DH + c * 8]);
            cpasync16(vs_b[0] + off, &g_vc[(size_t)(b * SS + r) * DH + c * 8]);
        }
        CP_COMMIT();
    }

    float oacc[2][8][4];
    #pragma unroll
    for (int m = 0; m < 2; m++)
        #pragma unroll
        for (int n = 0; n < 8; n++)
            #pragma unroll
            for (int i = 0; i < 4; i++) oacc[m][n][i] = 0.f;
    float rs_acc[2][2] = {{0.f, 0.f}, {0.f, 0.f}};

    for (int kt = 0; kt < nt; kt++) {
        const int p = kt & 1;
        const int k0 = kt * KT;
        CP_WAIT0();
        __syncthreads();

        if (kt + 1 < nt) {
            const int k1 = (kt + 1) * KT, p1 = p ^ 1;
            #pragma unroll
            for (int i = 0; i < 4; i++) {
                int idx = tid + i * 256;
                int r = idx >> 3, c = idx & 7;
                uint32_t off = ((uint32_t)(r * KV_STRH + c * 8)) * 2u;
                cpasync16(ks_b[p1] + off, &g_kc[(size_t)(b * SS + k1 + r) * DH + c * 8]);
                cpasync16(vs_b[p1] + off, &g_vc[(size_t)(b * SS + k1 + r) * DH + c * 8]);
            }
            CP_COMMIT();
        }

        float sacc[2][8][4];
        #pragma unroll
        for (int m = 0; m < 2; m++)
            #pragma unroll
            for (int n = 0; n < 8; n++)
                #pragma unroll
                for (int i = 0; i < 4; i++) sacc[m][n][i] = 0.f;

        #pragma unroll
        for (int s = 0; s < 4; s++) {
            #pragma unroll
            for (int nf = 0; nf < 8; nf++) {
                uint32_t b0, b1;
                uint32_t a = ks_b[p] +
                    ((uint32_t)((n0 + nf * 8 + (lane & 7)) * KV_STRH + 16 * s + (((lane >> 3) & 1) * 8))) * 2u;
                ldmx2(b0, b1, a);
                mma16(sacc[0][nf], qa[0][s], b0, b1);
                mma16(sacc[1][nf], qa[1][s], b0, b1);
            }
        }

        const int rem = count - k0;
        #pragma unroll
        for (int m = 0; m < 2; m++) {
            #pragma unroll
            for (int nf = 0; nf < 8; nf++) {
                int c = n0 + nf * 8 + 2 * tg;
                float mk0 = (c < rem) ? 1.f : 0.f;
                float mk1 = (c + 1 < rem) ? 1.f : 0.f;
                float p0 = ex2f(sacc[m][nf][0]) * mk0;
                float p1 = ex2f(sacc[m][nf][1]) * mk1;
                float p2 = ex2f(sacc[m][nf][2]) * mk0;
                float p3 = ex2f(sacc[m][nf][3]) * mk1;
                sacc[m][nf][0] = p0; sacc[m][nf][1] = p1;
                sacc[m][nf][2] = p2; sacc[m][nf][3] = p3;
                rs_acc[m][0] += p0 + p1;
                rs_acc[m][1] += p2 + p3;
            }
        }

        #pragma unroll
        for (int s = 0; s < 4; s++) {
            uint32_t pa0[4], pa1[4];
            pa0[0] = packh2(sacc[0][2 * s][0],     sacc[0][2 * s][1]);
            pa0[1] = packh2(sacc[0][2 * s][2],     sacc[0][2 * s][3]);
            pa0[2] = packh2(sacc[0][2 * s + 1][0], sacc[0][2 * s + 1][1]);
            pa0[3] = packh2(sacc[0][2 * s + 1][2], sacc[0][2 * s + 1][3]);
            pa1[0] = packh2(sacc[1][2 * s][0],     sacc[1][2 * s][1]);
            pa1[1] = packh2(sacc[1][2 * s][2],     sacc[1][2 * s][3]);
            pa1[2] = packh2(sacc[1][2 * s + 1][0], sacc[1][2 * s + 1][1]);
            pa1[3] = packh2(sacc[1][2 * s + 1][2], sacc[1][2 * s + 1][3]);
            #pragma unroll
            for (int nf = 0; nf < 8; nf++) {
                uint32_t b0, b1;
                uint32_t a = vs_b[p] +
                    ((uint32_t)((n0 + 16 * s + (lane & 15)) * KV_STRH + nf * 8)) * 2u;
                ldmx2t(b0, b1, a);
                mma16(oacc[0][nf], pa0, b0, b1);
                mma16(oacc[1][nf], pa1, b0, b1);
            }
        }
    }
    __syncthreads();

    #pragma unroll
    for (int m = 0; m < 2; m++)
        #pragma unroll
        for (int h = 0; h < 2; h++) {
            float v = rs_acc[m][h];
            v += __shfl_xor_sync(0xffffffffu, v, 1);
            v += __shfl_xor_sync(0xffffffffu, v, 2);
            if (tg == 0) lsum[warp_n * 128 + r0 + m * 16 + h * 8 + g] = v;
        }
    __syncthreads();

    if (warp_n == 0) {
        #pragma unroll
        for (int m = 0; m < 2; m++)
            #pragma unroll
            for (int nf = 0; nf < 8; nf++) {
                int r = r0 + m * 16 + g, c = nf * 8 + 2 * tg;
                *(float2*)&Obuf[r * OB_STR + c] =
                    make_float2(oacc[m][nf][0], oacc[m][nf][1]);
                *(float2*)&Obuf[(r + 8) * OB_STR + c] =
                    make_float2(oacc[m][nf][2], oacc[m][nf][3]);
            }
    }
    __syncthreads();
    if (warp_n == 1) {
        #pragma unroll
        for (int m = 0; m < 2; m++)
            #pragma unroll
            for (int nf = 0; nf < 8; nf++) {
                int r = r0 + m * 16 + g, c = nf * 8 + 2 * tg;
                float2 t0 = *(float2*)&Obuf[r * OB_STR + c];
                float2 t1 = *(float2*)&Obuf[(r + 8) * OB_STR + c];
                t0.x += oacc[m][nf][0]; t0.y += oacc[m][nf][1];
                t1.x += oacc[m][nf][2]; t1.y += oacc[m][nf][3];
                *(float2*)&Obuf[r * OB_STR + c] = t0;
                *(float2*)&Obuf[(r + 8) * OB_STR + c] = t1;
            }
    }
    __syncthreads();

    #pragma unroll
    for (int i = 0; i < 8; i++) {
        int idx = tid + i * 256;
        int r = idx >> 4, d4 = (idx & 15) * 4;
        float inv = 1.f / (lsum[r] + lsum[128 + r]);
        float4 v;
        v.x = Obuf[r * OB_STR + d4 + 0] * inv;
        v.y = Obuf[r * OB_STR + d4 + 1] * inv;
        v.z = Obuf[r * OB_STR + d4 + 2] * inv;
        v.w = Obuf[r * OB_STR + d4 + 3] * inv;
        *(float4*)&out[(size_t)(b * SS + q0 + r) * DH + d4] = v;
    }
}

// ===========================================================================
extern "C" void kernel_launch(void* const* d_in, const int* in_sizes, int n_in,
                              void* d_out, int out_size)
{
    const float* x  = (const float*)d_in[0];
    const int* mask = (const int*)d_in[1];
    const float* Wq = (const float*)d_in[2];
    const float* bq = (const float*)d_in[3];
    const float* Wk = (const float*)d_in[4];
    const float* bk = (const float*)d_in[5];
    const float* Wv = (const float*)d_in[6];
    const float* bv = (const float*)d_in[7];
    float* out = (float*)d_out;

    const int qsmem = 88064 + 192 * 4;   // 88832
    cudaFuncSetAttribute(qkv_mma, cudaFuncAttributeMaxDynamicSharedMemorySize, qsmem);
    qkv_mma<<<BB * SS / 128, 256, qsmem>>>(x, Wq, bq, Wk, bk, Wv, bv);

    compact_kernel<<<BB, 1024>>>(mask);

    const int smem = 73728 + 1024;   // 74752
    cudaFuncSetAttribute(attn_mma, cudaFuncAttributeMaxDynamicSharedMemorySize, smem);
    dim3 g2(SS / QT, BB);
    attn_mma<<<g2, 256, smem>>>(out);
}

// round 15
// speedup vs baseline: 1.3143x; 1.3012x over previous
#include <cuda_runtime.h>
#include <cuda_fp16.h>
#include <cstdint>

#define BB 4
#define SS 4096
#define DE 768
#define DH 64
#define QT 128
#define KT 128

// fp16 scratch for projected Q (pre-scaled), K, V.
__device__ __half g_qh[BB * SS * DH];
__device__ __half g_kh[BB * SS * DH];
__device__ __half g_vh[BB * SS * DH];
// compacted (unmasked-only, zero-padded to 128 multiple) K/V + counts
__device__ __half g_kc[BB * SS * DH];
__device__ __half g_vc[BB * SS * DH];
__device__ int    g_cnt[BB];
// fp16 fused weights [DE][192] (q|k|v)
__device__ __half g_wh[DE * 192];

// ---------------------------------------------------------------------------
// helpers
// ---------------------------------------------------------------------------
__device__ __forceinline__ float ex2f(float x) {
    float y; asm("ex2.approx.f32 %0, %1;" : "=f"(y) : "f"(x)); return y;
}
__device__ __forceinline__ void mma16(float* d, const uint32_t* a, uint32_t b0, uint32_t b1) {
    asm volatile(
        "mma.sync.aligned.m16n8k16.row.col.f32.f16.f16.f32 "
        "{%0,%1,%2,%3}, {%4,%5,%6,%7}, {%8,%9}, {%0,%1,%2,%3};"
        : "+f"(d[0]), "+f"(d[1]), "+f"(d[2]), "+f"(d[3])
        : "r"(a[0]), "r"(a[1]), "r"(a[2]), "r"(a[3]), "r"(b0), "r"(b1));
}
__device__ __forceinline__ void ldmx4(uint32_t* r, uint32_t addr) {
    asm volatile("ldmatrix.sync.aligned.m8n8.x4.shared.b16 {%0,%1,%2,%3}, [%4];"
        : "=r"(r[0]), "=r"(r[1]), "=r"(r[2]), "=r"(r[3]) : "r"(addr));
}
__device__ __forceinline__ void ldmx2(uint32_t& r0, uint32_t& r1, uint32_t addr) {
    asm volatile("ldmatrix.sync.aligned.m8n8.x2.shared.b16 {%0,%1}, [%2];"
        : "=r"(r0), "=r"(r1) : "r"(addr));
}
__device__ __forceinline__ void ldmx2t(uint32_t& r0, uint32_t& r1, uint32_t addr) {
    asm volatile("ldmatrix.sync.aligned.m8n8.x2.trans.shared.b16 {%0,%1}, [%2];"
        : "=r"(r0), "=r"(r1) : "r"(addr));
}
__device__ __forceinline__ uint32_t packh2(float lo, float hi) {
    __half2 h = __floats2half2_rn(lo, hi);
    return *(uint32_t*)&h;
}
__device__ __forceinline__ void cpasync16(uint32_t dst, const void* src) {
    asm volatile("cp.async.cg.shared.global [%0], [%1], 16;"
        :: "r"(dst), "l"(src) : "memory");
}
#define CP_COMMIT() asm volatile("cp.async.commit_group;" ::: "memory")
#define CP_WAIT0()  asm volatile("cp.async.wait_group 0;" ::: "memory")

// ===========================================================================
// Weight pre-conversion: [Wq|Wk|Wv] fp32 -> g_wh[DE][192] fp16. Tiny.
// ===========================================================================
__global__ __launch_bounds__(256) void wconv(
    const float* __restrict__ Wq, const float* __restrict__ Wk,
    const float* __restrict__ Wv)
{
    int idx = (blockIdx.x * 256 + threadIdx.x) * 4;        // over DE*192
    if (idx >= DE * 192) return;
    int k = idx / 192, c = idx % 192;
    int mtx = c >> 6, cc = c & 63;
    const float* W = (mtx == 0) ? Wq : (mtx == 1) ? Wk : Wv;
    float4 v = *(const float4*)&W[(size_t)k * DH + cc];
    uint2 u;
    u.x = packh2(v.x, v.y);
    u.y = packh2(v.z, v.w);
    *(uint2*)&g_wh[idx] = u;
}

// ===========================================================================
// Fused QKV: fp16 mma.sync + ldmatrix + cp.async, 64-row tiles, 2 CTAs/SM.
// C[16384,192] = X @ Wf + bias -> fp16 (Q pre-scaled by log2e/8).
// grid 256, 256 threads = 8 warps (warp_m = rows/32 of 64, warp_n = cols/48).
// ===========================================================================
#define XS_STR 36     // fp32 staging stride (floats)
#define XH_STR 40     // fp16 tile stride (halves)
#define WH_STR 200    // fp16 W tile stride (halves)

__global__ __launch_bounds__(256, 2) void qkv_mma(
    const float* __restrict__ X,
    const float* __restrict__ bq, const float* __restrict__ bk,
    const float* __restrict__ bv)
{
    extern __shared__ char qsm[];
    // Xs32[2]: 64x36 f32 = 9216 B each | Wh[2]: 32x200 half = 12800 B each
    // Xh: 64x40 half = 5120 B | bias 768 B
    float*  Xs32A[2] = { (float*)qsm, (float*)(qsm + 9216) };
    __half* WhA[2]   = { (__half*)(qsm + 18432), (__half*)(qsm + 31232) };
    __half* Xh       = (__half*)(qsm + 44032);
    float*  bsm      = (float*)(qsm + 49152);

    const int tid = threadIdx.x;
    const int wid = tid >> 5, lane = tid & 31;
    const int g = lane >> 2, tg = lane & 3;
    const int warp_m = wid & 1, warp_n = wid >> 1;
    const int r0 = warp_m * 32;
    const int n0 = warp_n * 48;
    const int m0 = blockIdx.x * 64;

    const uint32_t xs_b[2] = { (uint32_t)__cvta_generic_to_shared(Xs32A[0]),
                               (uint32_t)__cvta_generic_to_shared(Xs32A[1]) };
    const uint32_t wh_b[2] = { (uint32_t)__cvta_generic_to_shared(WhA[0]),
                               (uint32_t)__cvta_generic_to_shared(WhA[1]) };
    const uint32_t xh_b   = (uint32_t)__cvta_generic_to_shared(Xh);

    if (tid < 192)
        bsm[tid] = (tid < 64) ? bq[tid] : (tid < 128) ? bk[tid - 64] : bv[tid - 128];

    // ---- prefetch tile 0 ----
    {
        #pragma unroll
        for (int i = 0; i < 2; i++) {
            int idx = tid + i * 256;
            int r = idx >> 3, c4 = (idx & 7) * 4;
            cpasync16(xs_b[0] + ((uint32_t)(r * XS_STR + c4)) * 4u,
                      &X[(size_t)(m0 + r) * DE + c4]);
        }
        #pragma unroll
        for (int i = 0; i < 3; i++) {
            int idx = tid + i * 256;
            int kr = idx / 24, ch = (idx % 24) * 8;
            cpasync16(wh_b[0] + ((uint32_t)(kr * WH_STR + ch)) * 2u,
                      &g_wh[(size_t)kr * 192 + ch]);
        }
        CP_COMMIT();
    }

    float acc[2][6][4];
    #pragma unroll
    for (int m = 0; m < 2; m++)
        #pragma unroll
        for (int n = 0; n < 6; n++)
            #pragma unroll
            for (int i = 0; i < 4; i++) acc[m][n][i] = 0.f;

    for (int kc = 0; kc < DE / 32; kc++) {
        const int p = kc & 1;
        CP_WAIT0();
        __syncthreads();

        // prefetch next tile (overlaps everything below)
        if (kc + 1 < DE / 32) {
            const int k1 = (kc + 1) * 32, p1 = p ^ 1;
            #pragma unroll
            for (int i = 0; i < 2; i++) {
                int idx = tid + i * 256;
                int r = idx >> 3, c4 = (idx & 7) * 4;
                cpasync16(xs_b[p1] + ((uint32_t)(r * XS_STR + c4)) * 4u,
                          &X[(size_t)(m0 + r) * DE + k1 + c4]);
            }
            #pragma unroll
            for (int i = 0; i < 3; i++) {
                int idx = tid + i * 256;
                int kr = idx / 24, ch = (idx % 24) * 8;
                cpasync16(wh_b[p1] + ((uint32_t)(kr * WH_STR + ch)) * 2u,
                          &g_wh[(size_t)(k1 + kr) * 192 + ch]);
            }
            CP_COMMIT();
        }

        // ---- convert X tile fp32 -> fp16 (64x32, 8 elems/thread) ----
        {
            const float* Xs = Xs32A[p];
            int r = tid >> 2, c8 = (tid & 3) * 8;
            float4 v0 = *(const float4*)&Xs[r * XS_STR + c8];
            float4 v1 = *(const float4*)&Xs[r * XS_STR + c8 + 4];
            uint4 u;
            u.x = packh2(v0.x, v0.y); u.y = packh2(v0.z, v0.w);
            u.z = packh2(v1.x, v1.y); u.w = packh2(v1.z, v1.w);
            *(uint4*)&Xh[r * XH_STR + c8] = u;
        }
        __syncthreads();

        // ---- fragments + MMA (2 k16 steps) ----
        #pragma unroll
        for (int s = 0; s < 2; s++) {
            uint32_t a[2][4];
            #pragma unroll
            for (int m = 0; m < 2; m++) {
                uint32_t addr = xh_b +
                    ((uint32_t)((r0 + m * 16 + (lane & 15)) * XH_STR + 16 * s + ((lane >> 4) * 8))) * 2u;
                ldmx4(a[m], addr);
            }
            #pragma unroll
            for (int nf = 0; nf < 6; nf++) {
                uint32_t b0, b1;
                uint32_t addr = wh_b[p] +
                    ((uint32_t)((16 * s + (lane & 15)) * WH_STR + n0 + nf * 8)) * 2u;
                ldmx2t(b0, b1, addr);
                mma16(acc[0][nf], a[0], b0, b1);
                mma16(acc[1][nf], a[1], b0, b1);
            }
        }
    }

    const float SCL = 0.18033688011112042f;   // log2(e)/sqrt(64)
    #pragma unroll
    for (int m = 0; m < 2; m++) {
        #pragma unroll
        for (int nf = 0; nf < 6; nf++) {
            int col = n0 + nf * 8 + 2 * tg;
            int mtx = col >> 6, cc = col & 63;
            __half* C = (mtx == 0) ? g_qh : (mtx == 1) ? g_kh : g_vh;
            float s = (mtx == 0) ? SCL : 1.f;
            float b0 = bsm[col], b1 = bsm[col + 1];
            int ra = m0 + r0 + m * 16 + g;
            uint32_t u0 = packh2((acc[m][nf][0] + b0) * s, (acc[m][nf][1] + b1) * s);
            uint32_t u1 = packh2((acc[m][nf][2] + b0) * s, (acc[m][nf][3] + b1) * s);
            *(uint32_t*)&C[(size_t)ra * DH + cc] = u0;
            *(uint32_t*)&C[(size_t)(ra + 8) * DH + cc] = u1;
        }
    }
}

// ===========================================================================
// Compaction: gather unmasked K/V rows, zero-pad to 128 multiple.
// ===========================================================================
__global__ __launch_bounds__(1024) void compact_kernel(const int* __restrict__ mask)
{
    __shared__ int slist[SS];
    __shared__ int wsum[32];

    const int b = blockIdx.x;
    const int tid = threadIdx.x;
    const int lane = tid & 31, wid = tid >> 5;

    int k0 = tid * 4;
    int m0 = mask[b * SS + k0 + 0];
    int m1 = mask[b * SS + k0 + 1];
    int m2 = mask[b * SS + k0 + 2];
    int m3 = mask[b * SS + k0 + 3];
    int lsum = (m0 != 0) + (m1 != 0) + (m2 != 0) + (m3 != 0);

    int v = lsum;
    #pragma unroll
    for (int off = 1; off < 32; off <<= 1) {
        int t = __shfl_up_sync(0xffffffffu, v, off);
        if (lane >= off) v += t;
    }
    if (lane == 31) wsum[wid] = v;
    __syncthreads();
    if (wid == 0) {
        int w = wsum[lane];
        #pragma unroll
        for (int off = 1; off < 32; off <<= 1) {
            int t = __shfl_up_sync(0xffffffffu, w, off);
            if (lane >= off) w += t;
        }
        wsum[lane] = w;
    }
    __syncthreads();
    int base = (wid > 0 ? wsum[wid - 1] : 0) + (v - lsum);
    int p = base;
    if (m0) slist[p++] = k0 + 0;
    if (m1) slist[p++] = k0 + 1;
    if (m2) slist[p++] = k0 + 2;
    if (m3) slist[p++] = k0 + 3;
    const int count = wsum[31];
    if (tid == 0) g_cnt[b] = count;
    __syncthreads();

    const int padded = (count + 127) & ~127;
    for (int rb = 0; rb < padded; rb += 128) {
        int j = rb + (tid >> 3);
        int ch = tid & 7;
        if (j < padded) {
            uint4 z = make_uint4(0, 0, 0, 0);
            uint4 kv = z, vv = z;
            if (j < count) {
                int src = slist[j];
                kv = *(const uint4*)&g_kh[(size_t)(b * SS + src) * DH + ch * 8];
                vv = *(const uint4*)&g_vh[(size_t)(b * SS + src) * DH + ch * 8];
            }
            *(uint4*)&g_kc[(size_t)(b * SS + j) * DH + ch * 8] = kv;
            *(uint4*)&g_vc[(size_t)(b * SS + j) * DH + ch * 8] = vv;
        }
    }
}

// ===========================================================================
// Attention over compacted keys (unchanged).
// ===========================================================================
#define KV_STRH 72
#define OB_STR 72

__global__ __launch_bounds__(256, 1) void attn_mma(float* __restrict__ out)
{
    extern __shared__ char smc[];
    __half* KsA[2] = { (__half*)smc, (__half*)(smc + 18432) };
    __half* VsA[2] = { (__half*)(smc + 36864), (__half*)(smc + 55296) };
    float* lsum   = (float*)(smc + 73728);
    float* Obuf   = (float*)smc;
    __half* Qstg  = VsA[1];

    const int tid = threadIdx.x;
    const int wid = tid >> 5, lane = tid & 31;
    const int g = lane >> 2, tg = lane & 3;
    const int warp_m = wid & 3, warp_n = wid >> 2;
    const int r0 = warp_m * 32;
    const int n0 = warp_n * 64;
    const int b = blockIdx.y;
    const int q0 = blockIdx.x * QT;

    const int count = g_cnt[b];
    const int nt = (count + KT - 1) / KT;

    const uint32_t ks_b[2] = { (uint32_t)__cvta_generic_to_shared(KsA[0]),
                               (uint32_t)__cvta_generic_to_shared(KsA[1]) };
    const uint32_t vs_b[2] = { (uint32_t)__cvta_generic_to_shared(VsA[0]),
                               (uint32_t)__cvta_generic_to_shared(VsA[1]) };

    #pragma unroll
    for (int i = 0; i < 4; i++) {
        int idx = tid + i * 256;
        int r = idx >> 3, c = idx & 7;
        uint4 v = *(const uint4*)&g_qh[(size_t)(b * SS + q0 + r) * DH + c * 8];
        *(uint4*)&Qstg[r * KV_STRH + c * 8] = v;
    }
    __syncthreads();

    uint32_t qa[2][4][4];
    {
        uint32_t qbase = vs_b[1];
        #pragma unroll
        for (int m = 0; m < 2; m++)
            #pragma unroll
            for (int s = 0; s < 4; s++) {
                uint32_t a = qbase +
                    ((uint32_t)((r0 + m * 16 + (lane & 15)) * KV_STRH + 16 * s + ((lane >> 4) * 8))) * 2u;
                ldmx4(qa[m][s], a);
            }
    }
    __syncthreads();

    {
        #pragma unroll
        for (int i = 0; i < 4; i++) {
            int idx = tid + i * 256;
            int r = idx >> 3, c = idx & 7;
            uint32_t off = ((uint32_t)(r * KV_STRH + c * 8)) * 2u;
            cpasync16(ks_b[0] + off, &g_kc[(size_t)(b * SS + r) * DH + c * 8]);
            cpasync16(vs_b[0] + off, &g_vc[(size_t)(b * SS + r) * DH + c * 8]);
        }
        CP_COMMIT();
    }

    float oacc[2][8][4];
    #pragma unroll
    for (int m = 0; m < 2; m++)
        #pragma unroll
        for (int n = 0; n < 8; n++)
            #pragma unroll
            for (int i = 0; i < 4; i++) oacc[m][n][i] = 0.f;
    float rs_acc[2][2] = {{0.f, 0.f}, {0.f, 0.f}};

    for (int kt = 0; kt < nt; kt++) {
        const int p = kt & 1;
        const int k0 = kt * KT;
        CP_WAIT0();
        __syncthreads();

        if (kt + 1 < nt) {
            const int k1 = (kt + 1) * KT, p1 = p ^ 1;
            #pragma unroll
            for (int i = 0; i < 4; i++) {
                int idx = tid + i * 256;
                int r = idx >> 3, c = idx & 7;
                uint32_t off = ((uint32_t)(r * KV_STRH + c * 8)) * 2u;
                cpasync16(ks_b[p1] + off, &g_kc[(size_t)(b * SS + k1 + r) * DH + c * 8]);
                cpasync16(vs_b[p1] + off, &g_vc[(size_t)(b * SS + k1 + r) * DH + c * 8]);
            }
            CP_COMMIT();
        }

        float sacc[2][8][4];
        #pragma unroll
        for (int m = 0; m < 2; m++)
            #pragma unroll
            for (int n = 0; n < 8; n++)
                #pragma unroll
                for (int i = 0; i < 4; i++) sacc[m][n][i] = 0.f;

        #pragma unroll
        for (int s = 0; s < 4; s++) {
            #pragma unroll
            for (int nf = 0; nf < 8; nf++) {
                uint32_t b0, b1;
                uint32_t a = ks_b[p] +
                    ((uint32_t)((n0 + nf * 8 + (lane & 7)) * KV_STRH + 16 * s + (((lane >> 3) & 1) * 8))) * 2u;
                ldmx2(b0, b1, a);
                mma16(sacc[0][nf], qa[0][s], b0, b1);
                mma16(sacc[1][nf], qa[1][s], b0, b1);
            }
        }

        const int rem = count - k0;
        #pragma unroll
        for (int m = 0; m < 2; m++) {
            #pragma unroll
            for (int nf = 0; nf < 8; nf++) {
                int c = n0 + nf * 8 + 2 * tg;
                float mk0 = (c < rem) ? 1.f : 0.f;
                float mk1 = (c + 1 < rem) ? 1.f : 0.f;
                float p0 = ex2f(sacc[m][nf][0]) * mk0;
                float p1 = ex2f(sacc[m][nf][1]) * mk1;
                float p2 = ex2f(sacc[m][nf][2]) * mk0;
                float p3 = ex2f(sacc[m][nf][3]) * mk1;
                sacc[m][nf][0] = p0; sacc[m][nf][1] = p1;
                sacc[m][nf][2] = p2; sacc[m][nf][3] = p3;
                rs_acc[m][0] += p0 + p1;
                rs_acc[m][1] += p2 + p3;
            }
        }

        #pragma unroll
        for (int s = 0; s < 4; s++) {
            uint32_t pa0[4], pa1[4];
            pa0[0] = packh2(sacc[0][2 * s][0],     sacc[0][2 * s][1]);
            pa0[1] = packh2(sacc[0][2 * s][2],     sacc[0][2 * s][3]);
            pa0[2] = packh2(sacc[0][2 * s + 1][0], sacc[0][2 * s + 1][1]);
            pa0[3] = packh2(sacc[0][2 * s + 1][2], sacc[0][2 * s + 1][3]);
            pa1[0] = packh2(sacc[1][2 * s][0],     sacc[1][2 * s][1]);
            pa1[1] = packh2(sacc[1][2 * s][2],     sacc[1][2 * s][3]);
            pa1[2] = packh2(sacc[1][2 * s + 1][0], sacc[1][2 * s + 1][1]);
            pa1[3] = packh2(sacc[1][2 * s + 1][2], sacc[1][2 * s + 1][3]);
            #pragma unroll
            for (int nf = 0; nf < 8; nf++) {
                uint32_t b0, b1;
                uint32_t a = vs_b[p] +
                    ((uint32_t)((n0 + 16 * s + (lane & 15)) * KV_STRH + nf * 8)) * 2u;
                ldmx2t(b0, b1, a);
                mma16(oacc[0][nf], pa0, b0, b1);
                mma16(oacc[1][nf], pa1, b0, b1);
            }
        }
    }
    __syncthreads();

    #pragma unroll
    for (int m = 0; m < 2; m++)
        #pragma unroll
        for (int h = 0; h < 2; h++) {
            float v = rs_acc[m][h];
            v += __shfl_xor_sync(0xffffffffu, v, 1);
            v += __shfl_xor_sync(0xffffffffu, v, 2);
            if (tg == 0) lsum[warp_n * 128 + r0 + m * 16 + h * 8 + g] = v;
        }
    __syncthreads();

    if (warp_n == 0) {
        #pragma unroll
        for (int m = 0; m < 2; m++)
            #pragma unroll
            for (int nf = 0; nf < 8; nf++) {
                int r = r0 + m * 16 + g, c = nf * 8 + 2 * tg;
                *(float2*)&Obuf[r * OB_STR + c] =
                    make_float2(oacc[m][nf][0], oacc[m][nf][1]);
                *(float2*)&Obuf[(r + 8) * OB_STR + c] =
                    make_float2(oacc[m][nf][2], oacc[m][nf][3]);
            }
    }
    __syncthreads();
    if (warp_n == 1) {
        #pragma unroll
        for (int m = 0; m < 2; m++)
            #pragma unroll
            for (int nf = 0; nf < 8; nf++) {
                int r = r0 + m * 16 + g, c = nf * 8 + 2 * tg;
                float2 t0 = *(float2*)&Obuf[r * OB_STR + c];
                float2 t1 = *(float2*)&Obuf[(r + 8) * OB_STR + c];
                t0.x += oacc[m][nf][0]; t0.y += oacc[m][nf][1];
                t1.x += oacc[m][nf][2]; t1.y += oacc[m][nf][3];
                *(float2*)&Obuf[r * OB_STR + c] = t0;
                *(float2*)&Obuf[(r + 8) * OB_STR + c] = t1;
            }
    }
    __syncthreads();

    #pragma unroll
    for (int i = 0; i < 8; i++) {
        int idx = tid + i * 256;
        int r = idx >> 4, d4 = (idx & 15) * 4;
        float inv = 1.f / (lsum[r] + lsum[128 + r]);
        float4 v;
        v.x = Obuf[r * OB_STR + d4 + 0] * inv;
        v.y = Obuf[r * OB_STR + d4 + 1] * inv;
        v.z = Obuf[r * OB_STR + d4 + 2] * inv;
        v.w = Obuf[r * OB_STR + d4 + 3] * inv;
        *(float4*)&out[(size_t)(b * SS + q0 + r) * DH + d4] = v;
    }
}

// ===========================================================================
extern "C" void kernel_launch(void* const* d_in, const int* in_sizes, int n_in,
                              void* d_out, int out_size)
{
    const float* x  = (const float*)d_in[0];
    const int* mask = (const int*)d_in[1];
    const float* Wq = (const float*)d_in[2];
    const float* bq = (const float*)d_in[3];
    const float* Wk = (const float*)d_in[4];
    const float* bk = (const float*)d_in[5];
    const float* Wv = (const float*)d_in[6];
    const float* bv = (const float*)d_in[7];
    float* out = (float*)d_out;

    wconv<<<(DE * 192 / 4 + 255) / 256, 256>>>(Wq, Wk, Wv);

    const int qsmem = 49152 + 768;   // 49920
    cudaFuncSetAttribute(qkv_mma, cudaFuncAttributeMaxDynamicSharedMemorySize, qsmem);
    qkv_mma<<<BB * SS / 64, 256, qsmem>>>(x, bq, bk, bv);

    compact_kernel<<<BB, 1024>>>(mask);

    const int smem = 73728 + 1024;   // 74752
    cudaFuncSetAttribute(attn_mma, cudaFuncAttributeMaxDynamicSharedMemorySize, smem);
    dim3 g2(SS / QT, BB);
    attn_mma<<<g2, 256, smem>>>(out);
}